// round 15
// baseline (speedup 1.0000x reference)
#include <cuda_runtime.h>
#include <cuda_bf16.h>
#include <math.h>
#include <float.h>
#include <stdint.h>

#define NN 40000
#define FF 20
#define DD 128
#define SS 512
#define DISCOUNT 0.995f
#define ECOEF 0.1f

#define CHUNK 2048
#define NCH ((NN + CHUNK - 1)/CHUNK)   // 20

// Scratch (static device globals; no runtime allocation)
__device__ float    g_emb[(size_t)NN*DD];     // [N, D] fp32 (used by xgate)
__device__ unsigned g_emb16[(size_t)NN*DD/2]; // [N, D/2] bf16x2 (used by logits)
__device__ float    g_H[SS*DD];               // h_t used at step t
__device__ float    g_Xg[SS*4*DD];            // Wih@emb[idx_t] + bih + bhh
__device__ float    g_part[(size_t)SS*NCH*8];
__device__ int      g_mdt;                    // mask dtype: 0=u8,1=i32,2=f32

__device__ __forceinline__ void bffma(unsigned& acc, unsigned a, unsigned b) {
    asm("fma.rn.bf16x2 %0, %1, %2, %0;" : "+r"(acc) : "r"(a), "r"(b));
}
__device__ __forceinline__ unsigned packbf2(float lo, float hi) {
    __nv_bfloat162 v = __floats2bfloat162_rn(lo, hi);
    return *reinterpret_cast<unsigned*>(&v);
}
__device__ __forceinline__ float sum2(unsigned u) {
    __nv_bfloat162 v = *reinterpret_cast<__nv_bfloat162*>(&u);
    return __low2float(v) + __high2float(v);
}
__device__ __forceinline__ float tanh_fast(float x) {
    float y;
    asm("tanh.approx.f32 %0, %1;" : "=f"(y) : "f"(x));
    return y;
}

// ---------------------------------------------------------------------------
// Kernel 0: detect mask dtype from raw byte-phase pattern of sel_mask.
// ---------------------------------------------------------------------------
__global__ void detect_mask_dtype(const unsigned char* __restrict__ mask) {
    __shared__ int nzphase;
    if (threadIdx.x == 0) nzphase = 0;
    __syncthreads();
    int local = 0;
    for (int i = threadIdx.x; i < 16384; i += 128)
        if (mask[i]) local |= 1 << (i & 3);
    atomicOr(&nzphase, local);
    __syncthreads();
    if (threadIdx.x == 0) {
        int t;
        if (nzphase & 2)      t = 0;
        else if (nzphase & 1) t = 1;
        else                  t = 2;
        g_mdt = t;
    }
}

// ---------------------------------------------------------------------------
// Kernel A: emb = relu(feat@W1 + b1)@W2 + b2; emits fp32 + bf16x2 copies.
// ---------------------------------------------------------------------------
__global__ void mlp_kernel(const float* __restrict__ feat,
                           const float* __restrict__ W1, const float* __restrict__ b1,
                           const float* __restrict__ W2, const float* __restrict__ b2) {
    __shared__ float xs[8][FF];
    __shared__ float hid[8][DD];
    int d = threadIdx.x;           // 0..127
    int row0 = blockIdx.x * 8;
    for (int i = d; i < 8*FF; i += DD) {
        int r = i / FF, f = i % FF;
        xs[r][f] = feat[(size_t)(row0 + r)*FF + f];
    }
    __syncthreads();
    float b1d = b1[d];
    #pragma unroll
    for (int r = 0; r < 8; r++) {
        float acc = b1d;
        #pragma unroll
        for (int f = 0; f < FF; f++) acc = fmaf(xs[r][f], W1[f*DD + d], acc);
        hid[r][d] = fmaxf(acc, 0.f);
    }
    __syncthreads();
    float acc[8];
    float b2d = b2[d];
    #pragma unroll
    for (int r = 0; r < 8; r++) acc[r] = b2d;
    for (int k = 0; k < DD; k++) {
        float w = W2[k*DD + d];
        #pragma unroll
        for (int r = 0; r < 8; r++) acc[r] = fmaf(hid[r][k], w, acc[r]);
    }
    #pragma unroll
    for (int r = 0; r < 8; r++) {
        float o = acc[r];
        g_emb[(size_t)(row0 + r)*DD + d] = o;
        float hi = __shfl_down_sync(0xffffffffu, o, 1);
        if (!(d & 1))
            g_emb16[(size_t)(row0 + r)*(DD/2) + (d >> 1)] = packbf2(o, hi);
    }
}

// ---------------------------------------------------------------------------
// Kernel B: Xg[s] = Wih @ emb[sel_idx[s]] + bih + bhh   (one block per step)
// ---------------------------------------------------------------------------
__global__ void xgate_kernel(const int* __restrict__ sel_idx,
                             const float* __restrict__ Wih,
                             const float* __restrict__ bih,
                             const float* __restrict__ bhh) {
    int s = blockIdx.x;
    int r = threadIdx.x;       // 0..511
    __shared__ float x[DD];
    if (r < DD) x[r] = g_emb[(size_t)sel_idx[s]*DD + r];
    __syncthreads();
    float acc = bih[r] + bhh[r];
    const float4* w4 = (const float4*)(Wih + (size_t)r*DD);
    #pragma unroll 8
    for (int k = 0; k < DD/4; k++) {
        float4 w = w4[k];
        acc = fmaf(w.x, x[4*k+0], acc);
        acc = fmaf(w.y, x[4*k+1], acc);
        acc = fmaf(w.z, x[4*k+2], acc);
        acc = fmaf(w.w, x[4*k+3], acc);
    }
    g_Xg[(size_t)s*4*DD + r] = acc;
}

// ---------------------------------------------------------------------------
// Kernel C (v5): serial LSTM chain, quad-per-element layout.
// tid = e*4 + q; thread computes gate row q*128+e. Gate combine via 4 SHFL
// within the quad; nonlinearity pre-shuffle (1 tanh each); h double-buffered
// in smem -> single __syncthreads per step.
// ---------------------------------------------------------------------------
__global__ void __launch_bounds__(512, 1)
lstm_chain_kernel(const float* __restrict__ Whh,
                  const float* __restrict__ init_key,
                  const float* __restrict__ init_state) {
    __shared__ __align__(16) unsigned hbuf[2][DD/2];
    int tid = threadIdx.x;
    int e = tid >> 2, q = tid & 3;
    int row = q*DD + e;
    int lane = tid & 31;
    unsigned qb = lane & ~3u;

    // Pack this gate row's 128 weights into 64 bf16x2 registers.
    unsigned wr[64];
    const float2* wp = (const float2*)(Whh + (size_t)row*DD);
    #pragma unroll
    for (int j = 0; j < 64; j++) { float2 w = wp[j]; wr[j] = packbf2(w.x, w.y); }

    float creg = init_state[e];
    if (tid < DD/2) hbuf[0][tid] = packbf2(init_key[2*tid], init_key[2*tid+1]);
    if (q == 0) g_H[e] = init_key[e];
    __syncthreads();

    float xg = g_Xg[row];                       // prefetch t=0
    for (int t = 0; t < SS; t++) {
        const uint4* hq = (const uint4*)hbuf[t & 1];
        unsigned a0 = 0u, a1 = 0u, a2 = 0u, a3 = 0u;
        #pragma unroll
        for (int j = 0; j < 16; j++) {
            uint4 hv = hq[j];                   // broadcast LDS.128
            bffma(a0, wr[4*j+0], hv.x);
            bffma(a1, wr[4*j+1], hv.y);
            bffma(a2, wr[4*j+2], hv.z);
            bffma(a3, wr[4*j+3], hv.w);
        }
        float d = (sum2(a0)+sum2(a1)) + (sum2(a2)+sum2(a3)) + xg;
        if (t + 1 < SS) xg = g_Xg[(size_t)(t+1)*512 + row];

        // q==2 is the g-gate (tanh); others sigmoid = 0.5*tanh(0.5x)+0.5
        float arg = (q == 2) ? d : 0.5f*d;
        float tv = tanh_fast(arg);
        float v = (q == 2) ? tv : fmaf(0.5f, tv, 0.5f);
        float si = __shfl_sync(0xffffffffu, v, qb);
        float sf = __shfl_sync(0xffffffffu, v, qb | 1);
        float tg = __shfl_sync(0xffffffffu, v, qb | 2);
        float so = __shfl_sync(0xffffffffu, v, qb | 3);
        float c2 = sf*creg + si*tg;
        creg = c2;
        float h2 = so * tanh_fast(c2);
        float hp = __shfl_down_sync(0xffffffffu, h2, 4);   // h2 of element e+1
        if (t + 1 < SS && q == 0) {
            g_H[(size_t)(t+1)*DD + e] = h2;
            if (!(e & 1)) hbuf[(t+1) & 1][e >> 1] = packbf2(h2, hp);
        }
        __syncthreads();
    }
}

// ---------------------------------------------------------------------------
// Kernel D (v3): masked logits, row-per-lane with private online-LSE,
// shfl-butterfly merge. emb and h in bf16x2, chain-validated accumulators.
// ---------------------------------------------------------------------------
__global__ void logits_kernel(const unsigned char* __restrict__ mask,
                              const unsigned char* __restrict__ good) {
    int ch = blockIdx.x, s = blockIdx.y;
    int row0 = ch*CHUNK;
    int nrows = min(CHUNK, NN - row0);
    __shared__ uchar4 msk4[CHUNK/4];
    __shared__ uchar4 gd4[CHUNK/4];
    __shared__ unsigned short cidx[8][260];
    __shared__ __align__(16) unsigned h2sm[DD/2];
    __shared__ float wm[8], ws1[8], ws2[8], wce[8], wnp[8], wng[8];
    unsigned char* msk = (unsigned char*)msk4;
    unsigned char* gd  = (unsigned char*)gd4;
    int tid = threadIdx.x;        // 256
    int lane = tid & 31, warp = tid >> 5;
    size_t base = (size_t)s*NN + row0;
    int mdt = g_mdt;
    if (mdt == 0) {
        const uchar4* mp = (const uchar4*)(mask + base);
        const uchar4* gp = (const uchar4*)(good + base);
        int n4 = nrows >> 2;
        for (int i = tid; i < n4; i += 256) { msk4[i] = mp[i]; gd4[i] = gp[i]; }
    } else if (mdt == 1) {
        const int* mp = (const int*)mask + base;
        const int* gp = (const int*)good + base;
        for (int i = tid; i < nrows; i += 256) {
            msk[i] = (unsigned char)(mp[i] != 0);
            gd[i]  = (unsigned char)(gp[i] != 0);
        }
    } else {
        const float* mp = (const float*)mask + base;
        const float* gp = (const float*)good + base;
        for (int i = tid; i < nrows; i += 256) {
            msk[i] = (unsigned char)(mp[i] != 0.f);
            gd[i]  = (unsigned char)(gp[i] != 0.f);
        }
    }
    if (tid < DD/2) {
        const float* hS = g_H + (size_t)s*DD;
        h2sm[tid] = packbf2(hS[2*tid], hS[2*tid + 1]);
    }
    __syncthreads();

    // ballot compaction: rows [warp*256, warp*256+256)
    int rbeg = warp * 256;
    unsigned lmask = (1u << lane) - 1u;
    int cnt = 0;
    float ng = 0.f;
    #pragma unroll
    for (int b = 0; b < 8; b++) {
        int r = rbeg + b*32 + lane;
        int mv = (r < nrows) ? (int)msk[r] : 0;
        int gf = (mv && gd[r]) ? 1 : 0;
        unsigned bal = __ballot_sync(0xffffffffu, mv);
        unsigned bg  = __ballot_sync(0xffffffffu, gf);
        if (mv) cidx[warp][cnt + __popc(bal & lmask)] =
                    (unsigned short)(r | (gf << 15));
        cnt += __popc(bal);
        ng  += (float)__popc(bg);
    }

    // row-per-lane: lane handles compacted rows lane, lane+32, ...
    float m = -FLT_MAX, s1 = 0.f, s2 = 0.f, ce = 0.f;
    const uint4* hp4 = (const uint4*)h2sm;
    for (int i = lane; i < cnt; i += 32) {
        int e0 = cidx[warp][i];
        int r = e0 & 0x7FFF;
        const uint4* rp = (const uint4*)(g_emb16 + (size_t)(row0 + r)*(DD/2));
        unsigned a0 = 0u, a1 = 0u, a2 = 0u, a3 = 0u;
        #pragma unroll
        for (int j = 0; j < 16; j++) {
            uint4 ev = rp[j];
            uint4 hv = hp4[j];                  // broadcast
            bffma(a0, ev.x, hv.x);
            bffma(a1, ev.y, hv.y);
            bffma(a2, ev.z, hv.z);
            bffma(a3, ev.w, hv.w);
        }
        float l = (sum2(a0)+sum2(a1)) + (sum2(a2)+sum2(a3));
        if (e0 >> 15) ce += l;
        if (l <= m) {
            float e1 = expf(l - m);
            s1 += e1; s2 = fmaf(e1, l - m, s2);
        } else {
            float cc = expf(m - l);
            s2 = cc*s2 + cc*(m - l)*s1;
            s1 = fmaf(cc, s1, 1.f);
            m = l;
        }
    }

    // 32-lane butterfly LSE merge (-FLT_MAX sentinel keeps products finite)
    #pragma unroll
    for (int off = 16; off > 0; off >>= 1) {
        float mb  = __shfl_xor_sync(0xffffffffu, m,  off);
        float s1b = __shfl_xor_sync(0xffffffffu, s1, off);
        float s2b = __shfl_xor_sync(0xffffffffu, s2, off);
        float ceb = __shfl_xor_sync(0xffffffffu, ce, off);
        float mn = fmaxf(m, mb);
        float ca = expf(m - mn), cb = expf(mb - mn);
        s2 = ca*s2 + ca*(m - mn)*s1 + cb*s2b + cb*(mb - mn)*s1b;
        s1 = ca*s1 + cb*s1b;
        m = mn;
        ce += ceb;
    }

    if (lane == 0) {
        wm[warp]=m; ws1[warp]=s1; ws2[warp]=s2;
        wce[warp]=ce; wnp[warp]=(float)cnt; wng[warp]=ng;
    }
    __syncthreads();
    if (tid == 0) {
        float M=wm[0], S1=ws1[0], S2=ws2[0], CE=wce[0], NP=wnp[0], NG=wng[0];
        for (int w = 1; w < 8; w++) {
            float mb = wm[w];
            float mn = fmaxf(M, mb);
            float ca = expf(M - mn), cb = expf(mb - mn);
            S2 = ca*S2 + ca*(M-mn)*S1 + cb*ws2[w] + cb*(mb-mn)*ws1[w];
            S1 = ca*S1 + cb*ws1[w];
            M = mn;
            CE += wce[w]; NP += wnp[w]; NG += wng[w];
        }
        float* p = g_part + ((size_t)s*NCH + ch)*8;
        p[0]=M; p[1]=S1; p[2]=S2; p[3]=CE; p[4]=NP; p[5]=NG;
    }
}

// ---------------------------------------------------------------------------
// Kernel E: finalize — merge chunks per step, scan 'active', reduce loss
// ---------------------------------------------------------------------------
__global__ void finalize_kernel(float* out) {
    int s = threadIdx.x;     // 512
    const float* p = g_part + (size_t)s*NCH*8;
    float M=p[0], S1=p[1], S2=p[2], CE=p[3], NP=p[4], NG=p[5];
    for (int c = 1; c < NCH; c++) {
        const float* q = p + c*8;
        float mb = q[0];
        float mn = fmaxf(M, mb);
        float ca = expf(M - mn), cb = expf(mb - mn);
        S2 = ca*S2 + ca*(M-mn)*S1 + cb*q[2] + cb*(mb-mn)*q[1];
        S1 = ca*S1 + cb*q[1];
        M = mn;
        CE += q[3]; NP += q[4]; NG += q[5];
    }
    float nb = NP - NG;
    int active = (NG > 0.f && nb > 0.f) ? 1 : 0;
    float logZ = M + logf(S1);
    float ce = -(CE - NG*logZ) / fmaxf(NG, 1.f);
    float ment = (S2/S1 - logf(S1)) / logf(fmaxf(NP, 2.f));
    float A = active ? (nb/NP)*ce : 0.f;
    float B = active ? ECOEF*ment : 0.f;

    __shared__ int pre[SS];
    __shared__ float red[SS];
    pre[s] = active;
    __syncthreads();
    for (int off = 1; off < SS; off <<= 1) {
        int add = (s >= off) ? pre[s-off] : 0;
        __syncthreads();
        pre[s] += add;
        __syncthreads();
    }
    int cnt_before = pre[s] - active;
    float factor = powf(DISCOUNT, (float)cnt_before);
    red[s] = fmaf(factor, A, B);
    __syncthreads();
    for (int off = SS/2; off > 0; off >>= 1) {
        if (s < off) red[s] += red[s+off];
        __syncthreads();
    }
    if (s == 0) {
        float steps = (float)pre[SS-1];
        out[0] = red[0] / fmaxf(steps, 1.f);
    }
}

// ---------------------------------------------------------------------------
extern "C" void kernel_launch(void* const* d_in, const int* in_sizes, int n_in,
                              void* d_out, int out_size) {
    const float* feat          = (const float*)d_in[0];
    const unsigned char* smk   = (const unsigned char*)d_in[1];
    const unsigned char* gmk   = (const unsigned char*)d_in[2];
    const int* sel_idx         = (const int*)d_in[3];
    const float* W1            = (const float*)d_in[4];
    const float* b1            = (const float*)d_in[5];
    const float* W2            = (const float*)d_in[6];
    const float* b2            = (const float*)d_in[7];
    const float* init_key      = (const float*)d_in[8];
    const float* init_state    = (const float*)d_in[9];
    const float* Wih           = (const float*)d_in[10];
    const float* Whh           = (const float*)d_in[11];
    const float* bih           = (const float*)d_in[12];
    const float* bhh           = (const float*)d_in[13];

    detect_mask_dtype<<<1, 128>>>(smk);
    mlp_kernel<<<NN/8, DD>>>(feat, W1, b1, W2, b2);
    xgate_kernel<<<SS, 4*DD>>>(sel_idx, Wih, bih, bhh);
    lstm_chain_kernel<<<1, 512>>>(Whh, init_key, init_state);
    dim3 ge(NCH, SS);
    logits_kernel<<<ge, 256>>>(smk, gmk);
    finalize_kernel<<<1, SS>>>((float*)d_out);
}